// round 14
// baseline (speedup 1.0000x reference)
#include <cuda_runtime.h>
#include <cstdint>

// RandomizedOscillatorsNetwork: B=128, T=1024, I=64, H=512, dt=0.042
// R10: 2 CTAs per SM to hide the ~2600-cycle per-step latency tail behind the
// sibling CTA's matvec. CC=32 (W_s 74KB -> two ~101KB CTAs co-resident).
// Grid: 16 groups x 16 column slices = 256 CTAs, 256 threads each.
// Protocol identical to R1-verified: stcg publish -> bar -> tid0 red.release +
// poll -> bar -> coalesced ldcg refill -> bar. No threadfence.

#define DT_F      0.042f
#define B_        128
#define T_        1024
#define I_        64
#define H_        512
#define KAUG      576           // H_ + I_
#define NCOL      16            // column CTAs per group
#define NGRP      16            // batch groups
#define BC        8             // batches per CTA
#define CC        32            // columns per CTA
#define WPITCH    580           // 4*odd -> conflict-free float4 LDS
#define NTHREADS  256
#define KSLICES   8
#define KCHUNK4   18            // float4 per k-slice (72 floats)
#define AROW4     (KAUG / 4)    // 144
#define WROW4     (WPITCH / 4)  // 145

__device__ unsigned g_bar[NGRP];
__device__ float    g_hy_ex[2][NGRP][BC][H_];

__device__ __forceinline__ unsigned ld_acquire_u32(const unsigned* p) {
    unsigned v;
    asm volatile("ld.acquire.gpu.u32 %0, [%1];" : "=r"(v) : "l"(p) : "memory");
    return v;
}
__device__ __forceinline__ void red_release_add(unsigned* p, unsigned v) {
    asm volatile("red.release.gpu.global.add.u32 [%0], %1;" :: "l"(p), "r"(v) : "memory");
}

__global__ void ron_init_kernel() {
    if (threadIdx.x < NGRP) g_bar[threadIdx.x] = 0u;
}

__global__ void __launch_bounds__(NTHREADS, 2)
ron_scan_kernel(const float* __restrict__ x,      // [B, T, I]
                const float* __restrict__ x2h,    // [I, H]
                const float* __restrict__ h2h,    // [H, H]
                const float* __restrict__ bias,   // [H]
                const float* __restrict__ gamma_, // [H]
                const float* __restrict__ eps_,   // [H]
                float* __restrict__ out,          // [B*T*H] (+ optional [B*H] tail)
                int write_tail)
{
    extern __shared__ float smem[];
    float* W_s     = smem;                        // [CC][WPITCH] augmented weights, c-major
    float* a_s     = W_s + CC * WPITCH;           // [BC][KAUG]   hy | x_t
    float* partial = a_s + BC * KAUG;             // [KSLICES][BC][CC]

    const int tid = threadIdx.x;
    const int g   = blockIdx.x >> 4;     // batch group 0..15
    const int j   = blockIdx.x & 15;     // column slice 0..15
    const int b0  = g * BC;
    const int cg0 = j * CC;

    // roles: matvec (ks, c0) and elementwise (eb, ec) share the decomposition
    const int ks  = tid >> 5;            // 0..7 k-slice / batch
    const int c0  = tid & 31;            // 0..31 local column
    const int eb  = ks;                  // elementwise batch
    const int ec  = c0;                  // elementwise column

    // ---- Prologue ----
    for (int idx = tid; idx < KAUG * CC; idx += NTHREADS) {
        int k  = idx >> 5;               // 0..575
        int cc = idx & 31;
        float w = (k < H_) ? h2h[(size_t)k * H_ + cg0 + cc]
                           : x2h[(size_t)(k - H_) * H_ + cg0 + cc];
        W_s[cc * WPITCH + k] = w;
    }
    for (int idx = tid; idx < BC * H_; idx += NTHREADS) {
        int b = idx >> 9, k = idx & 511;
        a_s[b * KAUG + k] = 0.0f;
    }
    // x[t=0] staging: each thread covers (eb, ec) and (eb, ec+32)
    a_s[eb * KAUG + H_ + ec]      = x[((size_t)(b0 + eb) * T_ + 0) * I_ + ec];
    a_s[eb * KAUG + H_ + ec + 32] = x[((size_t)(b0 + eb) * T_ + 0) * I_ + ec + 32];

    const float bia = bias  [cg0 + ec];
    const float gam = gamma_[cg0 + ec];
    const float ep  = eps_  [cg0 + ec];

    __syncthreads();

    float hy_reg = 0.0f, hz = 0.0f;

    const float4* W4  = reinterpret_cast<const float4*>(W_s);
    const float4* A4  = reinterpret_cast<const float4*>(a_s);
    float4*       A4w = reinterpret_cast<float4*>(a_s);
    const size_t wbase = (size_t)c0 * WROW4 + (size_t)ks * KCHUNK4;

    for (int t = 0; t < T_; t++) {
        // prefetch next-step input (latency hidden under matvec)
        float xn0 = 0.0f, xn1 = 0.0f;
        if (t + 1 < T_) {
            xn0 = x[((size_t)(b0 + eb) * T_ + (t + 1)) * I_ + ec];
            xn1 = x[((size_t)(b0 + eb) * T_ + (t + 1)) * I_ + ec + 32];
        }

        // ---- Matvec: 1 col x 8 batches per thread over its 72-float k-chunk ----
        float acc[BC];
        #pragma unroll
        for (int b = 0; b < BC; b++) acc[b] = 0.0f;

        #pragma unroll
        for (int kb = 0; kb < KCHUNK4; kb++) {
            float4 w = W4[wbase + kb];
            #pragma unroll
            for (int b = 0; b < BC; b++) {
                float4 av = A4[b * AROW4 + ks * KCHUNK4 + kb];
                acc[b] = fmaf(av.x, w.x, acc[b]);
                acc[b] = fmaf(av.y, w.y, acc[b]);
                acc[b] = fmaf(av.z, w.z, acc[b]);
                acc[b] = fmaf(av.w, w.w, acc[b]);
            }
        }

        // ---- k-split partial stores ----
        #pragma unroll
        for (int b = 0; b < BC; b++)
            partial[ks * (BC * CC) + b * CC + c0] = acc[b];
        __syncthreads();   // #1

        // ---- reduce + oscillator update ----
        float v = 0.0f;
        #pragma unroll
        for (int s = 0; s < KSLICES; s++)
            v += partial[s * (BC * CC) + eb * CC + ec];

        float act = tanhf(v + bia);
        hz     = hz + DT_F * (act - gam * hy_reg - ep * hz);
        hy_reg = hy_reg + DT_F * hz;

        if (t + 1 == T_) {
            out[((size_t)(b0 + eb) * T_ + t) * H_ + cg0 + ec] = hy_reg;
            if (write_tail)
                out[(size_t)B_ * T_ * H_ + (size_t)(b0 + eb) * H_ + cg0 + ec] = hy_reg;
            break;
        }

        // ---- publish + arrive (peers' critical path first) ----
        __stcg(&g_hy_ex[t & 1][g][eb][cg0 + ec], hy_reg);
        __syncthreads();   // #2: all stcg issued before the release
        if (tid == 0) {
            red_release_add(&g_bar[g], 1u);
            const unsigned target = (unsigned)(NCOL * (t + 1));
            while (ld_acquire_u32(&g_bar[g]) < target) { }
        }
        // off-critical-path work overlaps tid0's poll
        out[((size_t)(b0 + eb) * T_ + t) * H_ + cg0 + ec] = hy_reg;
        a_s[eb * KAUG + H_ + ec]      = xn0;
        a_s[eb * KAUG + H_ + ec + 32] = xn1;
        __syncthreads();   // #3: poll done -> peers' hy visible

        // ---- refill all hy slices: 4 coalesced float4 ldcg per thread ----
        {
            const float4* G4 = reinterpret_cast<const float4*>(&g_hy_ex[t & 1][g][0][0]);
            #pragma unroll
            for (int i = 0; i < 4; i++) {
                int idx = tid + i * NTHREADS;        // 0..1023 float4
                int b   = idx >> 7;                  // 128 float4 per 512-float row
                int k4  = idx & 127;
                A4w[b * AROW4 + k4] = __ldcg(&G4[idx]);
            }
        }
        __syncthreads();   // #4: a_s ready for next matvec
    }
}

extern "C" void kernel_launch(void* const* d_in, const int* in_sizes, int n_in,
                              void* d_out, int out_size)
{
    const float* x      = (const float*)d_in[0];
    const float* x2h    = (const float*)d_in[1];
    const float* h2h    = (const float*)d_in[2];
    const float* bias   = (const float*)d_in[3];
    const float* gamma_ = (const float*)d_in[4];
    const float* eps_   = (const float*)d_in[5];
    float* out = (float*)d_out;

    // (32*580 + 8*576 + 8*8*32) * 4 = 100,864 B per CTA -> 2 CTAs/SM
    const int smem_bytes = (CC * WPITCH + BC * KAUG + KSLICES * BC * CC) * 4;
    cudaFuncSetAttribute(ron_scan_kernel,
                         cudaFuncAttributeMaxDynamicSharedMemorySize, smem_bytes);

    const int write_tail = (out_size > B_ * T_ * H_) ? 1 : 0;

    ron_init_kernel<<<1, 32>>>();
    ron_scan_kernel<<<NGRP * NCOL, NTHREADS, smem_bytes>>>(
        x, x2h, h2h, bias, gamma_, eps_, out, write_tail);
}